// round 16
// baseline (speedup 1.0000x reference)
#include <cuda_runtime.h>
#include <cuda_fp16.h>
#include <cstdint>

#define BB 16
#define DD 40
#define DPAD 48
#define NN 64512
#define KK 4
#define TPB 512                   // 16 warps
#define PTSB 512                  // points per tile
#define NTX 126                   // tiles per batch
#define NTILES (NTX * BB)         // 2016 total tiles
#define GRID 444                  // 148 SMs x 3 blocks  (one resident wave)
#define ROW (KK * DD + KK)        // 164
#define NEG_A_LOG2E (-7.21347520444482f)   // -alpha * log2(e)
#define PITCH 520                 // halves per sV row (1040B)
#define UPITCH 56                 // halves per sU row (112B)

// Scratch (__device__ globals: sanctioned no-alloc workaround)
__device__ float  g_acc[3][BB * ROW];          // triple-buffered centroid accumulators
__device__ __half g_Vh[(size_t)BB * DD * NN];  // fp16 shadow of Vact
__device__ float  g_v2[(size_t)BB * NN];       // per-point ||v||^2 (iteration-invariant)

// ---------------------------------------------------------------------------
// PTX helpers
// ---------------------------------------------------------------------------
__device__ __forceinline__ uint32_t smem_u32(const void* p) {
    uint32_t a;
    asm("{ .reg .u64 t; cvta.to.shared.u64 t, %1; cvt.u32.u64 %0, t; }" : "=r"(a) : "l"(p));
    return a;
}
__device__ __forceinline__ void ldsm_x4(uint32_t* r, uint32_t a) {
    asm volatile("ldmatrix.sync.aligned.m8n8.x4.shared.b16 {%0,%1,%2,%3}, [%4];"
                 : "=r"(r[0]), "=r"(r[1]), "=r"(r[2]), "=r"(r[3]) : "r"(a));
}
__device__ __forceinline__ void ldsm_x4_t(uint32_t* r, uint32_t a) {
    asm volatile("ldmatrix.sync.aligned.m8n8.x4.trans.shared.b16 {%0,%1,%2,%3}, [%4];"
                 : "=r"(r[0]), "=r"(r[1]), "=r"(r[2]), "=r"(r[3]) : "r"(a));
}
__device__ __forceinline__ void mma16816(float* c, const uint32_t* a, const uint32_t* b) {
    asm volatile("mma.sync.aligned.m16n8k16.row.col.f32.f16.f16.f32 "
                 "{%0,%1,%2,%3},{%4,%5,%6,%7},{%8,%9},{%0,%1,%2,%3};"
                 : "+f"(c[0]), "+f"(c[1]), "+f"(c[2]), "+f"(c[3])
                 : "r"(a[0]), "r"(a[1]), "r"(a[2]), "r"(a[3]), "r"(b[0]), "r"(b[1]));
}
__device__ __forceinline__ void mma16816_z(float* c, const uint32_t* a, const uint32_t* b) {
    asm volatile("mma.sync.aligned.m16n8k16.row.col.f32.f16.f16.f32 "
                 "{%0,%1,%2,%3},{%4,%5,%6,%7},{%8,%9},{%10,%10,%10,%10};"
                 : "=f"(c[0]), "=f"(c[1]), "=f"(c[2]), "=f"(c[3])
                 : "r"(a[0]), "r"(a[1]), "r"(a[2]), "r"(a[3]), "r"(b[0]), "r"(b[1]),
                   "f"(0.0f));
}
__device__ __forceinline__ void cp_async16(uint32_t dst, const void* src) {
    asm volatile("cp.async.cg.shared.global [%0], [%1], 16;" :: "r"(dst), "l"(src) : "memory");
}
__device__ __forceinline__ void cp_async_wait_all() {
    asm volatile("cp.async.commit_group;\n\tcp.async.wait_group 0;" ::: "memory");
}
__device__ __forceinline__ float sqrt_approx(float x) {
    float r;
    asm("sqrt.approx.f32 %0, %1;" : "=f"(r) : "f"(x));
    return r;
}
__device__ __forceinline__ float tanh_fast(float x) {
    float e = __expf(fminf(2.0f * x, 80.0f));
    return 1.0f - __fdividef(2.0f, e + 1.0f);
}

// ---------------------------------------------------------------------------
// init: detect idx dtype; U0 = tanh(V[b,:,idx]) into g_acc[2] (accum format:
// V_Y = u, sumY = 1); zero g_acc[0] (dst of iter 0).
// ---------------------------------------------------------------------------
__global__ void init_kernel(const float* __restrict__ V, const void* __restrict__ idx_raw) {
    __shared__ int is64;
    const int t = threadIdx.x;  // 64 threads, one per (b,k)
    if (t == 0) {
        const int* p = (const int*)idx_raw;   // first 256B safe for either dtype
        int all0 = 1;
        for (int i = 1; i < 64; i += 2)
            if (p[i] != 0) { all0 = 0; break; }
        is64 = all0;
    }
    __syncthreads();

    for (int i = t; i < BB * ROW; i += 64) g_acc[0][i] = 0.0f;

    long long idxv;
    if (is64) idxv = ((const long long*)idx_raw)[t];
    else      idxv = (long long)((const int*)idx_raw)[t];

    const int b = t / KK;
    const int k = t % KK;
    const float* vb = V + (size_t)b * DD * NN;
    for (int d = 0; d < DD; d++)
        g_acc[2][b * ROW + k * DD + d] = tanhf(vb[(size_t)d * NN + (size_t)idxv]);
    g_acc[2][b * ROW + KK * DD + k] = 1.0f;
}

// ---------------------------------------------------------------------------
// km iteration, persistent: grid 444 (one wave), each block loops tiles
// tile = bid, bid+444, ... over the flattened (b, x) tile space.
// Per-tile body identical to R11:
//   MODE 0: fused transform (V -> tanh -> vact fp32 + shadow + v2).
//   MODE 1: single-group cp.async staging (max MLP, one wait).
//   phaseA: C(16k x pts) = Upad(16x48) @ sV(48 x pts); sU col40=-u2/2,
//           col41=residual; sV rows 40,41 = ones  =>  d2 = v2 - 2c
//   in-register softmax -> phaseB: C2 = Y @ sV^T; col 40 (ones) = sumY.
// Pad rows 40-47 are written once (epilogue alias touches only rows 0-11).
// ---------------------------------------------------------------------------
template <int MODE>
__global__ __launch_bounds__(TPB, 3) void km_mma(const float* __restrict__ V,
                                                 float* __restrict__ vact,
                                                 int srcIdx, int dstIdx, int zeroIdx) {
    const int t = threadIdx.x;
    const int w = t >> 5;      // 0..15
    const int l = t & 31;

    __shared__ __align__(16) __half sV[DPAD][PITCH];    // 49.9 KB (rows 0-11 aliased)
    __shared__ __align__(16) __half sU[16][UPITCH];     // 1.75 KB (rows 4-15 unused)
    __shared__ __align__(16) float  sv2[PTSB];          // 2 KB

    const uint32_t smV = smem_u32(&sV[0][0]);
    const uint32_t smU = smem_u32(&sU[0][0]);

    // pad rows 40-47 once: rows 40,41 = 1.0, rows 42-47 = 0
    {
        const int r = 40 + (t >> 6);
        const int c = (t & 63) * 8;
        const uint32_t pv = (r <= 41) ? 0x3C003C00u : 0u;
        uint4 q; q.x = pv; q.y = pv; q.z = pv; q.w = pv;
        *(uint4*)&sV[r][c] = q;
    }

    for (int tile = blockIdx.x; tile < NTILES; tile += GRID) {
        const int b = tile / NTX;
        const int n0 = (tile - b * NTX) * PTSB;

        // ---- staging first (MODE 1): one group, all rows in flight
        if (MODE == 1) {
            const __half* gv = g_Vh + (size_t)b * DD * NN + n0;
#pragma unroll
            for (int i = 0; i < 5; i++) {             // 2560 chunks = 40 rows x 64
                const int idx = t + TPB * i;
                const int d = idx >> 6, c = idx & 63;
                cp_async16(smV + (uint32_t)(d * (PITCH * 2) + 16 * c),
                           gv + (size_t)d * NN + 8 * c);
            }
            sv2[t] = g_v2[(size_t)b * NN + n0 + t];
        }

        // ---- prologue: U for this b; u2 folded as extra columns
        const float* src = g_acc[srcIdx] + b * ROW;
        if (t < 160) {
            const int k = t / DD;
            const float inv = __fdividef(1.0f, src[KK * DD + k] + 1e-9f);
            sU[k][t - k * DD] = __float2half(src[t] * inv);
        } else if (t < 164) {
            const int k = t - 160;
            const float inv = __fdividef(1.0f, src[KK * DD + k] + 1e-9f);
            float u2 = 0.0f;
#pragma unroll
            for (int d = 0; d < DD; d++) {
                const float uh = __half2float(__float2half(src[k * DD + d] * inv));
                u2 += uh * uh;
            }
            const float m = -0.5f * u2;
            const __half h1 = __float2half(m);
            sU[k][DD]     = h1;                                  // col 40 (ones row)
            sU[k][DD + 1] = __float2half(m - __half2float(h1));  // col 41 residual
        } else if (t < 188) {      // zero sU rows 0-3, cols 42-47
            const int r = (t - 164) / 6, c = 42 + (t - 164) % 6;
            sU[r][c] = __float2half(0.0f);
        }
        if (t < ROW) g_acc[zeroIdx][b * ROW + t] = 0.0f;

        if (MODE == 0) {
            // fused transform: thread t owns point n0+t across all d
            const float* vp = V + (size_t)b * DD * NN + n0 + t;
            float* wp = vact + (size_t)b * DD * NN + n0 + t;
            __half* hp = g_Vh + (size_t)b * DD * NN + n0 + t;
            float v2 = 0.0f;
#pragma unroll 8
            for (int d = 0; d < DD; d++) {
                const float f = tanh_fast(vp[(size_t)d * NN]);
                wp[(size_t)d * NN] = f;
                const __half h = __float2half(f);
                hp[(size_t)d * NN] = h;
                sV[d][t] = h;
                v2 += f * f;
            }
            sv2[t] = v2;
            g_v2[(size_t)b * NN + n0 + t] = v2;
        } else {
            cp_async_wait_all();
        }
        __syncthreads();

        // unified accumulator: phaseA uses cc[0..15], phaseB all 24
        float cc[24];

        // ---- phaseA
#pragma unroll
        for (int ks = 0; ks < 3; ks++) {
            uint32_t ua[4];
            ldsm_x4(ua, smU + (uint32_t)((l & 15) * (UPITCH * 2) + (l >> 4) * 16 + ks * 32));
#pragma unroll
            for (int jp = 0; jp < 2; jp++) {
                uint32_t bb[4];
                ldsm_x4_t(bb, smV + (uint32_t)((16 * ks + (l & 15)) * (PITCH * 2)
                                               + (32 * w + 16 * jp + 8 * (l >> 4)) * 2));
                if (ks == 0) {
                    mma16816_z(&cc[4 * (2 * jp)],     ua, bb);
                    mma16816_z(&cc[4 * (2 * jp + 1)], ua, bb + 2);
                } else {
                    mma16816(&cc[4 * (2 * jp)],     ua, bb);
                    mma16816(&cc[4 * (2 * jp + 1)], ua, bb + 2);
                }
            }
        }

        // ---- in-register softmax over k (lanes g, g+4, g+8, g+12 = k 0..3)
        uint32_t h[4];
        const int g2 = 2 * (l & 3);
#pragma unroll
        for (int j = 0; j < 4; j++) {
            const int p0 = 8 * (4 * w + j) + g2;
            const float2 vv = *(const float2*)&sv2[p0];
            float e0 = exp2f(NEG_A_LOG2E *
                             sqrt_approx(fmaxf(vv.x - 2.0f * cc[4 * j],     1e-12f)));
            float e1 = exp2f(NEG_A_LOG2E *
                             sqrt_approx(fmaxf(vv.y - 2.0f * cc[4 * j + 1], 1e-12f)));
            float s0 = e0, s1 = e1;
            s0 += __shfl_xor_sync(0xffffffffu, s0, 4);
            s1 += __shfl_xor_sync(0xffffffffu, s1, 4);
            s0 += __shfl_xor_sync(0xffffffffu, s0, 8);
            s1 += __shfl_xor_sync(0xffffffffu, s1, 8);
            float y0 = __fdividef(e0, s0);
            float y1 = __fdividef(e1, s1);
            if (l >= 16) { y0 = 0.0f; y1 = 0.0f; }   // pad rows k=4..7
            const __half2 hh = __floats2half2_rn(y0, y1);
            h[j] = *(const uint32_t*)&hh;
        }

        // ---- phaseB: C2 = Y @ V^T
#pragma unroll
        for (int s = 0; s < 2; s++) {
            const uint32_t a[4] = { h[2 * s], 0u, h[2 * s + 1], 0u };
            const int ks = 2 * w + s;
#pragma unroll
            for (int ntp = 0; ntp < 3; ntp++) {
                uint32_t bb[4];
                ldsm_x4(bb, smV + (uint32_t)((8 * (2 * ntp + (l >> 4)) + (l & 7)) * (PITCH * 2)
                                             + (16 * ks + 8 * ((l >> 3) & 1)) * 2));
                if (s == 0) {
                    mma16816_z(&cc[4 * (2 * ntp)],     a, bb);
                    mma16816_z(&cc[4 * (2 * ntp + 1)], a, bb + 2);
                } else {
                    mma16816(&cc[4 * (2 * ntp)],     a, bb);
                    mma16816(&cc[4 * (2 * ntp + 1)], a, bb + 2);
                }
            }
        }

        // ---- epilogue: reduce via smem aliased onto sV rows 0-11, atomics
        __syncthreads();                      // all sV reads complete before alias
        float* sPtl = (float*)&sV[0][0];      // [16][4][48] f32 = 12.3 KB
        if (l < 16) {
            const int r = l >> 2;
#pragma unroll
            for (int nt = 0; nt < 6; nt++) {
                float2 p; p.x = cc[4 * nt]; p.y = cc[4 * nt + 1];
                *(float2*)&sPtl[w * 192 + r * 48 + 8 * nt + g2] = p;
            }
        }
        __syncthreads();
        if (t < ROW) {
            const int r = t / 41, ccol = t % 41;
            const int cs = (ccol < DD) ? ccol : 40;   // col 40 (ones) = sumY
            float s = 0.0f;
#pragma unroll
            for (int ww = 0; ww < 16; ww++) s += sPtl[ww * 192 + r * 48 + cs];
            float* dst = g_acc[dstIdx] + b * ROW;
            if (ccol < DD) atomicAdd(&dst[r * DD + ccol], s);
            else           atomicAdd(&dst[KK * DD + r], s);
        }
        __syncthreads();                      // sPtl reads done; sU/sV reusable
    }
}

// ---------------------------------------------------------------------------
// final: A = V_Y/(sumY+eps); mask = softmax_k(A . Vact), reading the fp16
// shadow, 4 points/thread (uint2 loads, float4 stores)
// ---------------------------------------------------------------------------
#define MTPB 256
#define MPTS 1024
#define MBLK (NN / MPTS)   // 63
__global__ __launch_bounds__(MTPB) void mask_kernel(float* __restrict__ mask,
                                                    float* __restrict__ outA,
                                                    int srcIdx) {
    const int b = blockIdx.y;
    const int t = threadIdx.x;

    __shared__ float sA[KK * DD];
    if (t < KK * DD) {
        const int k = t / DD;
        const float* src = g_acc[srcIdx] + b * ROW;
        const float a = src[t] / (src[KK * DD + k] + 1e-9f);
        sA[t] = a;
        if (blockIdx.x == 0) outA[b * KK * DD + t] = a;
    }
    __syncthreads();

    const int n0 = blockIdx.x * MPTS + 4 * t;
    const __half* gv = g_Vh + (size_t)b * DD * NN + n0;
    float dot[KK][4];
#pragma unroll
    for (int k = 0; k < KK; k++)
#pragma unroll
        for (int j = 0; j < 4; j++) dot[k][j] = 0.0f;
#pragma unroll
    for (int d = 0; d < DD; d++) {
        const uint2 q = *(const uint2*)(gv + (size_t)d * NN);
        const float2 f01 = __half22float2(*(const __half2*)&q.x);
        const float2 f23 = __half22float2(*(const __half2*)&q.y);
#pragma unroll
        for (int k = 0; k < KK; k++) {
            const float a = sA[k * DD + d];
            dot[k][0] += f01.x * a; dot[k][1] += f01.y * a;
            dot[k][2] += f23.x * a; dot[k][3] += f23.y * a;
        }
    }
#pragma unroll
    for (int j = 0; j < 4; j++) {
        float m = fmaxf(fmaxf(dot[0][j], dot[1][j]), fmaxf(dot[2][j], dot[3][j]));
        float e[KK], s = 0.0f;
#pragma unroll
        for (int k = 0; k < KK; k++) { e[k] = __expf(dot[k][j] - m); s += e[k]; }
        const float inv = __fdividef(1.0f, s);
#pragma unroll
        for (int k = 0; k < KK; k++) dot[k][j] = e[k] * inv;   // reuse as output
    }
#pragma unroll
    for (int k = 0; k < KK; k++) {
        float4 o; o.x = dot[k][0]; o.y = dot[k][1]; o.z = dot[k][2]; o.w = dot[k][3];
        *(float4*)(mask + (size_t)b * KK * NN + (size_t)k * NN + n0) = o;
    }
}

// ---------------------------------------------------------------------------
extern "C" void kernel_launch(void* const* d_in, const int* in_sizes, int n_in,
                              void* d_out, int out_size) {
    const float* V = (const float*)d_in[0];
    const void* idx = d_in[1];

    float* out  = (float*)d_out;
    float* mask = out;                                 // (B, K, N)
    float* vact = out + (size_t)BB * KK * NN;          // (B, D, N)
    float* outA = vact + (size_t)BB * DD * NN;         // (B, K, D)

    init_kernel<<<1, 64>>>(V, idx);

    for (int it = 0; it < 10; it++) {
        const int dstIdx  = it % 3;
        const int srcIdx  = (it + 2) % 3;   // it=0 reads g_acc[2] written by init
        const int zeroIdx = (it + 1) % 3;
        if (it == 0) km_mma<0><<<GRID, TPB>>>(V, vact, srcIdx, dstIdx, zeroIdx);
        else         km_mma<1><<<GRID, TPB>>>(nullptr, nullptr, srcIdx, dstIdx, zeroIdx);
    }
    // after it=9, accumulators live in buffer 0
    mask_kernel<<<dim3(MBLK, BB), MTPB>>>(mask, outA, 0);
}

// round 17
// speedup vs baseline: 1.5644x; 1.5644x over previous
#include <cuda_runtime.h>
#include <cuda_fp16.h>
#include <cstdint>

#define BB 16
#define DD 40
#define DPAD 48
#define NN 64512
#define KK 4
#define TPB 512                   // 16 warps
#define PTSB 512                  // points per block (1 per thread)
#define NBLK (NN / PTSB)          // 126
#define ROW (KK * DD + KK)        // 164
#define NEG_A_LOG2E (-7.21347520444482f)   // -alpha * log2(e)
#define PITCH 520                 // halves per sV row (1040B)
#define UPITCH 56                 // halves per sU row (112B)

// Scratch (__device__ globals: sanctioned no-alloc workaround)
__device__ float  g_acc[3][BB * ROW];          // triple-buffered centroid accumulators
__device__ __half g_Vh[(size_t)BB * DD * NN];  // fp16 shadow of Vact
__device__ float  g_v2[(size_t)BB * NN];       // per-point ||v||^2 (iteration-invariant)

// ---------------------------------------------------------------------------
// PTX helpers
// ---------------------------------------------------------------------------
__device__ __forceinline__ uint32_t smem_u32(const void* p) {
    uint32_t a;
    asm("{ .reg .u64 t; cvta.to.shared.u64 t, %1; cvt.u32.u64 %0, t; }" : "=r"(a) : "l"(p));
    return a;
}
__device__ __forceinline__ void ldsm_x4(uint32_t* r, uint32_t a) {
    asm volatile("ldmatrix.sync.aligned.m8n8.x4.shared.b16 {%0,%1,%2,%3}, [%4];"
                 : "=r"(r[0]), "=r"(r[1]), "=r"(r[2]), "=r"(r[3]) : "r"(a));
}
__device__ __forceinline__ void ldsm_x4_t(uint32_t* r, uint32_t a) {
    asm volatile("ldmatrix.sync.aligned.m8n8.x4.trans.shared.b16 {%0,%1,%2,%3}, [%4];"
                 : "=r"(r[0]), "=r"(r[1]), "=r"(r[2]), "=r"(r[3]) : "r"(a));
}
__device__ __forceinline__ void mma16816(float* c, const uint32_t* a, const uint32_t* b) {
    asm volatile("mma.sync.aligned.m16n8k16.row.col.f32.f16.f16.f32 "
                 "{%0,%1,%2,%3},{%4,%5,%6,%7},{%8,%9},{%0,%1,%2,%3};"
                 : "+f"(c[0]), "+f"(c[1]), "+f"(c[2]), "+f"(c[3])
                 : "r"(a[0]), "r"(a[1]), "r"(a[2]), "r"(a[3]), "r"(b[0]), "r"(b[1]));
}
__device__ __forceinline__ void mma16816_z(float* c, const uint32_t* a, const uint32_t* b) {
    asm volatile("mma.sync.aligned.m16n8k16.row.col.f32.f16.f16.f32 "
                 "{%0,%1,%2,%3},{%4,%5,%6,%7},{%8,%9},{%10,%10,%10,%10};"
                 : "=f"(c[0]), "=f"(c[1]), "=f"(c[2]), "=f"(c[3])
                 : "r"(a[0]), "r"(a[1]), "r"(a[2]), "r"(a[3]), "r"(b[0]), "r"(b[1]),
                   "f"(0.0f));
}
__device__ __forceinline__ void cp_async16(uint32_t dst, const void* src) {
    asm volatile("cp.async.cg.shared.global [%0], [%1], 16;" :: "r"(dst), "l"(src) : "memory");
}
__device__ __forceinline__ void cp_async_wait_all() {
    asm volatile("cp.async.commit_group;\n\tcp.async.wait_group 0;" ::: "memory");
}
__device__ __forceinline__ float sqrt_approx(float x) {
    float r;
    asm("sqrt.approx.f32 %0, %1;" : "=f"(r) : "f"(x));
    return r;
}
__device__ __forceinline__ float tanh_fast(float x) {
    float e = __expf(fminf(2.0f * x, 80.0f));
    return 1.0f - __fdividef(2.0f, e + 1.0f);
}

// ---------------------------------------------------------------------------
// init: detect idx dtype; U0 = tanh(V[b,:,idx]) into g_acc[2] (accum format:
// V_Y = u, sumY = 1); zero g_acc[0] (dst of iter 0).
// ---------------------------------------------------------------------------
__global__ void init_kernel(const float* __restrict__ V, const void* __restrict__ idx_raw) {
    __shared__ int is64;
    const int t = threadIdx.x;  // 64 threads, one per (b,k)
    if (t == 0) {
        const int* p = (const int*)idx_raw;   // first 256B safe for either dtype
        int all0 = 1;
        for (int i = 1; i < 64; i += 2)
            if (p[i] != 0) { all0 = 0; break; }
        is64 = all0;
    }
    __syncthreads();

    for (int i = t; i < BB * ROW; i += 64) g_acc[0][i] = 0.0f;

    long long idxv;
    if (is64) idxv = ((const long long*)idx_raw)[t];
    else      idxv = (long long)((const int*)idx_raw)[t];

    const int b = t / KK;
    const int k = t % KK;
    const float* vb = V + (size_t)b * DD * NN;
    for (int d = 0; d < DD; d++)
        g_acc[2][b * ROW + k * DD + d] = tanhf(vb[(size_t)d * NN + (size_t)idxv]);
    g_acc[2][b * ROW + KK * DD + k] = 1.0f;
}

// ---------------------------------------------------------------------------
// km iteration: 512 points / 512 threads (16 warps) per block.
// MODE 0: fused transform (raw V -> tanh -> Vact fp32 + fp16 shadow + v2).
// MODE 1: stage fp16 shadow via cp.async.cg (single group, max MLP).
// phaseA: C(16k x pts) = Upad(16x48) @ sV(48 x pts); sU col40 = -u2/2,
//         col41 = residual; sV rows 40,41 = ones  =>  d2 = v2 - 2c.
// softmax in-register (shfl over k), pack to half2 -> phaseB A fragments.
// phaseB: C2(16k x 48d) = Y @ sV^T; sV row 40 ones => C2[k][40] = sumY.
// Epilogue reduction buffer ALIASES sV.
// ---------------------------------------------------------------------------
template <int MODE>
__global__ __launch_bounds__(TPB, 3) void km_mma(const float* __restrict__ V,
                                                 float* __restrict__ vact,
                                                 int srcIdx, int dstIdx, int zeroIdx) {
    const int b = blockIdx.y;
    const int t = threadIdx.x;
    const int w = t >> 5;      // 0..15
    const int l = t & 31;
    const int n0 = blockIdx.x * PTSB;

    __shared__ __align__(16) __half sV[DPAD][PITCH];    // 49.9 KB (aliased by sPtl later)
    __shared__ __align__(16) __half sU[16][UPITCH];     // 1.75 KB (rows 4-15 unused)
    __shared__ __align__(16) float  sv2[PTSB];          // 2 KB

    const uint32_t smV = smem_u32(&sV[0][0]);

    // ---- issue async staging first (MODE 1): overlaps with prologue
    if (MODE == 1) {
        const __half* gv = g_Vh + (size_t)b * DD * NN + n0;
#pragma unroll
        for (int i = 0; i < 5; i++) {                 // 2560 chunks = 40 rows x 64
            const int idx = t + TPB * i;
            const int d = idx >> 6, c = idx & 63;
            cp_async16(smV + (uint32_t)(d * (PITCH * 2) + 16 * c),
                       gv + (size_t)d * NN + 8 * c);
        }
        sv2[t] = g_v2[(size_t)b * NN + n0 + t];
    }

    // ---- prologue: U from previous accumulators; u2 folded as extra columns
    const float* src = g_acc[srcIdx] + b * ROW;
    if (t < 160) {
        const int k = t / DD;
        const float inv = __fdividef(1.0f, src[KK * DD + k] + 1e-9f);
        sU[k][t - k * DD] = __float2half(src[t] * inv);
    } else if (t < 164) {
        const int k = t - 160;
        const float inv = __fdividef(1.0f, src[KK * DD + k] + 1e-9f);
        float u2 = 0.0f;
#pragma unroll
        for (int d = 0; d < DD; d++) {
            const float uh = __half2float(__float2half(src[k * DD + d] * inv));
            u2 += uh * uh;
        }
        const float m = -0.5f * u2;
        const __half h1 = __float2half(m);
        sU[k][DD]     = h1;                                  // col 40 (ones row)
        sU[k][DD + 1] = __float2half(m - __half2float(h1));  // col 41 residual
    } else if (t < 188) {          // zero sU rows 0-3, cols 42-47
        const int r = (t - 164) / 6, c = 42 + (t - 164) % 6;
        sU[r][c] = __float2half(0.0f);
    }
    if (t < ROW) g_acc[zeroIdx][b * ROW + t] = 0.0f;

    // sV pad rows 40-47, cols 0-511: rows 40,41 = 1.0, rows 42-47 = 0
    {
        const int r = 40 + (t >> 6);
        const int c = (t & 63) * 8;
        const uint32_t pv = (r <= 41) ? 0x3C003C00u : 0u;
        uint4 q; q.x = pv; q.y = pv; q.z = pv; q.w = pv;
        *(uint4*)&sV[r][c] = q;
    }

    if (MODE == 0) {
        // fused transform: thread t owns point n0+t across all d
        const float* vp = V + (size_t)b * DD * NN + n0 + t;
        float* wp = vact + (size_t)b * DD * NN + n0 + t;
        __half* hp = g_Vh + (size_t)b * DD * NN + n0 + t;
        float v2 = 0.0f;
#pragma unroll 8
        for (int d = 0; d < DD; d++) {
            const float f = tanh_fast(vp[(size_t)d * NN]);
            wp[(size_t)d * NN] = f;
            const __half h = __float2half(f);
            hp[(size_t)d * NN] = h;
            sV[d][t] = h;
            v2 += f * f;
        }
        sv2[t] = v2;
        g_v2[(size_t)b * NN + n0 + t] = v2;
    } else {
        cp_async_wait_all();
    }
    __syncthreads();

    const uint32_t smU = smem_u32(&sU[0][0]);

    // unified accumulator array: phaseA uses cc[0..15], phaseB all 24
    float cc[24];

    // ---- phaseA: per warp, C tiles j=0..3 cover its 32 points
#pragma unroll
    for (int ks = 0; ks < 3; ks++) {
        uint32_t ua[4];
        ldsm_x4(ua, smU + (uint32_t)((l & 15) * (UPITCH * 2) + (l >> 4) * 16 + ks * 32));
#pragma unroll
        for (int jp = 0; jp < 2; jp++) {
            uint32_t bb[4];
            ldsm_x4_t(bb, smV + (uint32_t)((16 * ks + (l & 15)) * (PITCH * 2)
                                           + (32 * w + 16 * jp + 8 * (l >> 4)) * 2));
            if (ks == 0) {
                mma16816_z(&cc[4 * (2 * jp)],     ua, bb);
                mma16816_z(&cc[4 * (2 * jp + 1)], ua, bb + 2);
            } else {
                mma16816(&cc[4 * (2 * jp)],     ua, bb);
                mma16816(&cc[4 * (2 * jp + 1)], ua, bb + 2);
            }
        }
    }

    // ---- in-register softmax over k (lanes g, g+4, g+8, g+12 hold k=0..3)
    uint32_t h[4];
    const int g2 = 2 * (l & 3);
#pragma unroll
    for (int j = 0; j < 4; j++) {
        const int p0 = 8 * (4 * w + j) + g2;
        const float2 vv = *(const float2*)&sv2[p0];
        float e0 = exp2f(NEG_A_LOG2E * sqrt_approx(fmaxf(vv.x - 2.0f * cc[4 * j],     1e-12f)));
        float e1 = exp2f(NEG_A_LOG2E * sqrt_approx(fmaxf(vv.y - 2.0f * cc[4 * j + 1], 1e-12f)));
        float s0 = e0, s1 = e1;
        s0 += __shfl_xor_sync(0xffffffffu, s0, 4);
        s1 += __shfl_xor_sync(0xffffffffu, s1, 4);
        s0 += __shfl_xor_sync(0xffffffffu, s0, 8);
        s1 += __shfl_xor_sync(0xffffffffu, s1, 8);
        float y0 = __fdividef(e0, s0);
        float y1 = __fdividef(e1, s1);
        if (l >= 16) { y0 = 0.0f; y1 = 0.0f; }   // pad rows k=4..7
        const __half2 hh = __floats2half2_rn(y0, y1);
        h[j] = *(const uint32_t*)&hh;
    }

    // ---- phaseB: C2 = Y @ V^T ; A-fragments straight from h[]
#pragma unroll
    for (int s = 0; s < 2; s++) {
        const uint32_t a[4] = { h[2 * s], 0u, h[2 * s + 1], 0u };
        const int ks = 2 * w + s;   // points chunk [16ks, 16ks+16) = this warp's
#pragma unroll
        for (int ntp = 0; ntp < 3; ntp++) {
            uint32_t bb[4];
            ldsm_x4(bb, smV + (uint32_t)((8 * (2 * ntp + (l >> 4)) + (l & 7)) * (PITCH * 2)
                                         + (16 * ks + 8 * ((l >> 3) & 1)) * 2));
            if (s == 0) {
                mma16816_z(&cc[4 * (2 * ntp)],     a, bb);
                mma16816_z(&cc[4 * (2 * ntp + 1)], a, bb + 2);
            } else {
                mma16816(&cc[4 * (2 * ntp)],     a, bb);
                mma16816(&cc[4 * (2 * ntp + 1)], a, bb + 2);
            }
        }
    }

    // ---- epilogue: cross-warp reduce via smem ALIASED onto sV, then atomics
    __syncthreads();                      // all sV reads complete before alias
    float* sPtl = (float*)&sV[0][0];      // [16][4][48] f32 = 12.3 KB
    if (l < 16) {
        const int r = l >> 2;
#pragma unroll
        for (int nt = 0; nt < 6; nt++) {
            float2 p; p.x = cc[4 * nt]; p.y = cc[4 * nt + 1];
            *(float2*)&sPtl[w * 192 + r * 48 + 8 * nt + g2] = p;
        }
    }
    __syncthreads();
    if (t < ROW) {
        const int r = t / 41, ccol = t % 41;
        const int cs = (ccol < DD) ? ccol : 40;   // col 40 (ones) = sumY
        float s = 0.0f;
#pragma unroll
        for (int ww = 0; ww < 16; ww++) s += sPtl[ww * 192 + r * 48 + cs];
        float* dst = g_acc[dstIdx] + b * ROW;
        if (ccol < DD) atomicAdd(&dst[r * DD + ccol], s);
        else           atomicAdd(&dst[KK * DD + r], s);
    }
}

// ---------------------------------------------------------------------------
// final: A = V_Y/(sumY+eps); mask = softmax_k(A . Vact), reading the fp16
// shadow, 4 points/thread (uint2 loads, float4 stores)
// ---------------------------------------------------------------------------
#define MTPB 256
#define MPTS 1024
#define MBLK (NN / MPTS)   // 63
__global__ __launch_bounds__(MTPB) void mask_kernel(float* __restrict__ mask,
                                                    float* __restrict__ outA,
                                                    int srcIdx) {
    const int b = blockIdx.y;
    const int t = threadIdx.x;

    __shared__ float sA[KK * DD];
    if (t < KK * DD) {
        const int k = t / DD;
        const float* src = g_acc[srcIdx] + b * ROW;
        const float a = src[t] / (src[KK * DD + k] + 1e-9f);
        sA[t] = a;
        if (blockIdx.x == 0) outA[b * KK * DD + t] = a;
    }
    __syncthreads();

    const int n0 = blockIdx.x * MPTS + 4 * t;
    const __half* gv = g_Vh + (size_t)b * DD * NN + n0;
    float dot[KK][4];
#pragma unroll
    for (int k = 0; k < KK; k++)
#pragma unroll
        for (int j = 0; j < 4; j++) dot[k][j] = 0.0f;
#pragma unroll
    for (int d = 0; d < DD; d++) {
        const uint2 q = *(const uint2*)(gv + (size_t)d * NN);
        const float2 f01 = __half22float2(*(const __half2*)&q.x);
        const float2 f23 = __half22float2(*(const __half2*)&q.y);
#pragma unroll
        for (int k = 0; k < KK; k++) {
            const float a = sA[k * DD + d];
            dot[k][0] += f01.x * a; dot[k][1] += f01.y * a;
            dot[k][2] += f23.x * a; dot[k][3] += f23.y * a;
        }
    }
#pragma unroll
    for (int j = 0; j < 4; j++) {
        float m = fmaxf(fmaxf(dot[0][j], dot[1][j]), fmaxf(dot[2][j], dot[3][j]));
        float e[KK], s = 0.0f;
#pragma unroll
        for (int k = 0; k < KK; k++) { e[k] = __expf(dot[k][j] - m); s += e[k]; }
        const float inv = __fdividef(1.0f, s);
#pragma unroll
        for (int k = 0; k < KK; k++) dot[k][j] = e[k] * inv;   // reuse as output
    }
#pragma unroll
    for (int k = 0; k < KK; k++) {
        float4 o; o.x = dot[k][0]; o.y = dot[k][1]; o.z = dot[k][2]; o.w = dot[k][3];
        *(float4*)(mask + (size_t)b * KK * NN + (size_t)k * NN + n0) = o;
    }
}

// ---------------------------------------------------------------------------
extern "C" void kernel_launch(void* const* d_in, const int* in_sizes, int n_in,
                              void* d_out, int out_size) {
    const float* V = (const float*)d_in[0];
    const void* idx = d_in[1];

    float* out  = (float*)d_out;
    float* mask = out;                                 // (B, K, N)
    float* vact = out + (size_t)BB * KK * NN;          // (B, D, N)
    float* outA = vact + (size_t)BB * DD * NN;         // (B, K, D)

    init_kernel<<<1, 64>>>(V, idx);

    dim3 grid(NBLK, BB);
    for (int it = 0; it < 10; it++) {
        const int dstIdx  = it % 3;
        const int srcIdx  = (it + 2) % 3;   // it=0 reads g_acc[2] written by init
        const int zeroIdx = (it + 1) % 3;
        if (it == 0) km_mma<0><<<grid, TPB>>>(V, vact, srcIdx, dstIdx, zeroIdx);
        else         km_mma<1><<<grid, TPB>>>(nullptr, nullptr, srcIdx, dstIdx, zeroIdx);
    }
    // after it=9, accumulators live in buffer 0
    mask_kernel<<<dim3(MBLK, BB), MTPB>>>(mask, outA, 0);
}